// round 13
// baseline (speedup 1.0000x reference)
#include <cuda_runtime.h>
#include <cuda_bf16.h>
#include <cstdint>

// ============================================================================
// Shifted-window attention pipeline:
//   K0: split X / qkvw / projw into bf16 (hi, lo) pairs        (elementwise)
//   K1: qkv(hi,lo) = X @ qkvw^T + qkvb   (bf16 3-term MMA, 128x128 tile,
//        K-chunk 32, 2-stage cp.async, 2 CTAs/SM)
//   K2: per-(window, head-pair) attention via mma.sync, grid (1024, 6)
//   K3: out = attno @ projw^T + projb    (same GEMM, fp32 out)
// ============================================================================

#define KDIM 384
#define NTOKENS 50176   // 16*56*56 = 392*128

static __device__ unsigned short g_qhi[(size_t)NTOKENS * 1152];
static __device__ unsigned short g_qlo[(size_t)NTOKENS * 1152];
static __device__ unsigned short g_xhi[(size_t)NTOKENS * 384];
static __device__ unsigned short g_xlo[(size_t)NTOKENS * 384];
static __device__ unsigned short g_ahi[(size_t)NTOKENS * 384];
static __device__ unsigned short g_alo[(size_t)NTOKENS * 384];
static __device__ unsigned short g_whi[1152 * 384];
static __device__ unsigned short g_wlo[1152 * 384];
static __device__ unsigned short g_phi[384 * 384];
static __device__ unsigned short g_plo[384 * 384];

__device__ __forceinline__ uint32_t smem_u32(const void* p) {
    uint32_t a;
    asm("{ .reg .u64 t; cvta.to.shared.u64 t, %1; cvt.u32.u64 %0, t; }"
        : "=r"(a) : "l"(p));
    return a;
}
#define LDM4(r0, r1, r2, r3, addr)                                           \
    asm volatile("ldmatrix.sync.aligned.m8n8.x4.shared.b16 {%0,%1,%2,%3}, [%4];" \
                 : "=r"(r0), "=r"(r1), "=r"(r2), "=r"(r3) : "r"(addr))
#define LDM4T(r0, r1, r2, r3, addr)                                          \
    asm volatile("ldmatrix.sync.aligned.m8n8.x4.trans.shared.b16 {%0,%1,%2,%3}, [%4];" \
                 : "=r"(r0), "=r"(r1), "=r"(r2), "=r"(r3) : "r"(addr))
#define MMA_BF16(c, a, b)                                                    \
    asm volatile("mma.sync.aligned.m16n8k16.row.col.f32.bf16.bf16.f32 "      \
                 "{%0,%1,%2,%3}, {%4,%5,%6,%7}, {%8,%9}, {%0,%1,%2,%3};"     \
                 : "+f"((c)[0]), "+f"((c)[1]), "+f"((c)[2]), "+f"((c)[3])    \
                 : "r"((a)[0]), "r"((a)[1]), "r"((a)[2]), "r"((a)[3]),       \
                   "r"((b)[0]), "r"((b)[1]))
#define CPA16(dst, src)                                                      \
    asm volatile("cp.async.ca.shared.global [%0], [%1], 16;" :: "r"(dst), "l"(src))
#define CPA_COMMIT() asm volatile("cp.async.commit_group;")
#define CPA_WAIT1()  asm volatile("cp.async.wait_group 1;")
#define CPA_WAIT0()  asm volatile("cp.async.wait_group 0;")

__device__ __forceinline__ void cvt_split(float x, unsigned short& h,
                                          unsigned short& l) {
    __nv_bfloat16 bh = __float2bfloat16_rn(x);
    h = __bfloat16_as_ushort(bh);
    l = __bfloat16_as_ushort(__float2bfloat16_rn(x - __bfloat162float(bh)));
}

// ============================================================================
// K0: fp32 -> bf16 hi/lo split
// ============================================================================
__global__ void __launch_bounds__(256)
split_bf16_kernel(const float4* __restrict__ in, ushort4* __restrict__ hi,
                  ushort4* __restrict__ lo, int n4)
{
    int i = blockIdx.x * 256 + threadIdx.x;
    if (i >= n4) return;
    float4 v = in[i];
    ushort4 h, l;
    cvt_split(v.x, h.x, l.x);
    cvt_split(v.y, h.y, l.y);
    cvt_split(v.z, h.z, l.z);
    cvt_split(v.w, h.w, l.w);
    hi[i] = h;
    lo[i] = l;
}

// ============================================================================
// K1/K3 GEMM (unchanged from R12 — proven 405 us / tensor 54%)
// ============================================================================
#define GSTR 40
#define TILE_US (128 * GSTR)            // 5120
#define STAGE_US (4 * TILE_US)          // 20480
#define GSMEM_BYTES (2 * STAGE_US * 2)  // 81920

__global__ void __launch_bounds__(256, 2)
gemm_bf16x3_kernel(const unsigned short* __restrict__ Ahi_g,
                   const unsigned short* __restrict__ Alo_g,
                   const unsigned short* __restrict__ Bhi_g,
                   const unsigned short* __restrict__ Blo_g,
                   const float* __restrict__ bias, float* __restrict__ C,
                   unsigned short* __restrict__ Chi,
                   unsigned short* __restrict__ Clo,
                   int ncols, int qflag)
{
    extern __shared__ __align__(16) unsigned short gsm[];

    const int tid  = threadIdx.x;
    const int lane = tid & 31;
    const int wid  = tid >> 5;
    const int wm   = wid & 3;
    const int wn   = wid >> 2;
    const int mbase = blockIdx.x * 128;
    const int nbase = blockIdx.y * 128;
    const uint32_t sbase = smem_u32(gsm);

    const int lr = lane & 7, lq = lane >> 3;
    const uint32_t aoff =
        (uint32_t)((((lq & 1) * 8 + lr) * GSTR + (lq >> 1) * 8) * 2);
    const uint32_t boff =
        (uint32_t)((((lq >> 1) * 8 + lr) * GSTR + (lq & 1) * 8) * 2);

    float c[2][8][4];
    #pragma unroll
    for (int mt = 0; mt < 2; ++mt)
        #pragma unroll
        for (int nt = 0; nt < 8; ++nt)
            #pragma unroll
            for (int i = 0; i < 4; ++i) c[mt][nt][i] = 0.f;

    auto prefetch = [&](int sbuf, int kc) {
        const uint32_t st = sbase + (uint32_t)sbuf * (STAGE_US * 2);
        #pragma unroll
        for (int j = 0; j < 8; ++j) {
            int cch = tid + 256 * j;
            int tile = cch >> 9;
            int rc = cch & 511;
            int row = rc >> 2, c8 = rc & 3;
            uint32_t doff = (uint32_t)(tile * (TILE_US * 2) + row * 80 + c8 * 16);
            const unsigned short* srcb;
            size_t idx;
            if (tile < 2) {
                srcb = (tile & 1) ? Alo_g : Ahi_g;
                idx = (size_t)(mbase + row) * KDIM + kc * 32 + c8 * 8;
            } else {
                srcb = (tile & 1) ? Blo_g : Bhi_g;
                idx = (size_t)(nbase + row) * KDIM + kc * 32 + c8 * 8;
            }
            CPA16(st + doff, srcb + idx);
        }
        CPA_COMMIT();
    };

    prefetch(0, 0);

    for (int kc = 0; kc < 12; ++kc) {
        if (kc + 1 < 12) {
            prefetch((kc + 1) & 1, kc + 1);
            CPA_WAIT1();
        } else {
            CPA_WAIT0();
        }
        __syncthreads();

        const uint32_t st = sbase + (uint32_t)(kc & 1) * (STAGE_US * 2);
        const uint32_t sAhi = st;
        const uint32_t sAlo = st + TILE_US * 2;
        const uint32_t sBhi = st + 2 * TILE_US * 2;
        const uint32_t sBlo = st + 3 * TILE_US * 2;

        #pragma unroll
        for (int ks = 0; ks < 2; ++ks) {
            const uint32_t kb = (uint32_t)(ks * 32);
            uint32_t ah[2][4], al[2][4];
            #pragma unroll
            for (int mt = 0; mt < 2; ++mt) {
                uint32_t base = (uint32_t)((wm * 32 + mt * 16) * (GSTR * 2)) + kb;
                LDM4(ah[mt][0], ah[mt][1], ah[mt][2], ah[mt][3], sAhi + base + aoff);
                LDM4(al[mt][0], al[mt][1], al[mt][2], al[mt][3], sAlo + base + aoff);
            }
            #pragma unroll
            for (int ntp = 0; ntp < 4; ++ntp) {
                uint32_t bh[2][2], bl[2][2];
                uint32_t base = (uint32_t)((wn * 64 + ntp * 16) * (GSTR * 2)) + kb;
                LDM4(bh[0][0], bh[0][1], bh[1][0], bh[1][1], sBhi + base + boff);
                LDM4(bl[0][0], bl[0][1], bl[1][0], bl[1][1], sBlo + base + boff);
                #pragma unroll
                for (int mt = 0; mt < 2; ++mt)
                    #pragma unroll
                    for (int j = 0; j < 2; ++j) {
                        MMA_BF16(c[mt][ntp * 2 + j], ah[mt], bh[j]);
                        MMA_BF16(c[mt][ntp * 2 + j], ah[mt], bl[j]);
                        MMA_BF16(c[mt][ntp * 2 + j], al[mt], bh[j]);
                    }
            }
        }
        __syncthreads();
    }

    const float qscale = 0.17677669529663687f;
    #pragma unroll
    for (int mt = 0; mt < 2; ++mt) {
        #pragma unroll
        for (int nt = 0; nt < 8; ++nt) {
            int row0 = mbase + wm * 32 + mt * 16 + (lane >> 2);
            int col  = nbase + wn * 64 + nt * 8 + (lane & 3) * 2;
            float sc = (qflag && col < 384) ? qscale : 1.0f;
            float b0 = __ldg(bias + col), b1 = __ldg(bias + col + 1);
            float v00 = (c[mt][nt][0] + b0) * sc;
            float v01 = (c[mt][nt][1] + b1) * sc;
            float v10 = (c[mt][nt][2] + b0) * sc;
            float v11 = (c[mt][nt][3] + b1) * sc;
            if (Chi != nullptr) {
                unsigned short h0, l0, h1, l1;
                cvt_split(v00, h0, l0); cvt_split(v01, h1, l1);
                *(ushort2*)(Chi + (size_t)row0 * ncols + col) = make_ushort2(h0, h1);
                *(ushort2*)(Clo + (size_t)row0 * ncols + col) = make_ushort2(l0, l1);
                cvt_split(v10, h0, l0); cvt_split(v11, h1, l1);
                *(ushort2*)(Chi + (size_t)(row0 + 8) * ncols + col) = make_ushort2(h0, h1);
                *(ushort2*)(Clo + (size_t)(row0 + 8) * ncols + col) = make_ushort2(l0, l1);
            } else {
                *(float2*)(C + (size_t)row0 * ncols + col) = make_float2(v00, v01);
                *(float2*)(C + (size_t)(row0 + 8) * ncols + col) = make_float2(v10, v11);
            }
        }
    }
}

// ============================================================================
// K2: attention, one CTA per (window, head-pair). grid (1024, 6).
// ============================================================================
#define T2_US 4608            // 64*72
#define K2_QH 0
#define K2_QL (1*T2_US)
#define K2_KH (2*T2_US)
#define K2_KL (3*T2_US)
#define K2_VH (4*T2_US)
#define K2_VL (5*T2_US)
#define K2_PH (6*T2_US)
#define K2_PL (7*T2_US)
#define K2_ATT_F 18432
#define K2_BIAS_F (K2_ATT_F + 3712)
#define K2_INTS_F (K2_BIAS_F + 338)
#define K2_SMEM_BYTES 90752

__global__ void __launch_bounds__(256, 2)
swin_attn_mma_kernel(const unsigned short* __restrict__ qhi,
                     const unsigned short* __restrict__ qlo,
                     const float* __restrict__ table,
                     unsigned short* __restrict__ ahi,
                     unsigned short* __restrict__ alo)
{
    extern __shared__ float sf[];
    unsigned short* su = (unsigned short*)sf;
    float* attnS = sf + K2_ATT_F;          // [64][58]
    float* biasP = sf + K2_BIAS_F;         // [2][169]
    int*   tokS  = (int*)(sf + K2_INTS_F);
    int*   regS  = tokS + 49;
    int*   rowS  = regS + 49;
    int*   colS  = rowS + 49;

    const int tid  = threadIdx.x;
    const int lane = tid & 31;
    const int wid  = tid >> 5;
    const int mt   = wid & 3;
    const int nh   = wid >> 2;
    const int w    = blockIdx.x;
    const int hp   = blockIdx.y;          // head pair 0..5
    const int b    = w >> 6;
    const int wi   = w & 63;
    const int wr   = wi >> 3;
    const int wc   = wi & 7;

    const uint32_t sb = smem_u32(su);
    const int lr = lane & 7, lq = lane >> 3;
    const uint32_t aoff =
        (uint32_t)((((lq & 1) * 8 + lr) * 72 + (lq >> 1) * 8) * 2);
    const uint32_t boff =
        (uint32_t)((((lq >> 1) * 8 + lr) * 72 + (lq & 1) * 8) * 2);

    // zero all 8 tiles (pad rows/cols stay zero)
    {
        unsigned long long* z = (unsigned long long*)su;
        for (int i = tid; i < 8 * T2_US / 4; i += 256) z[i] = 0ull;
    }

    if (tid < 49) {
        int tr = tid / 7, tc = tid - tr * 7;
        rowS[tid] = tr; colS[tid] = tc;
        int gr = wr * 7 + tr, gc = wc * 7 + tc;
        int rh = (gr < 49) ? 0 : (gr < 53 ? 1 : 2);
        int rw = (gc < 49) ? 0 : (gc < 53 ? 1 : 2);
        regS[tid] = rh * 3 + rw;
        int sr = gr + 3; if (sr >= 56) sr -= 56;
        int sc = gc + 3; if (sc >= 56) sc -= 56;
        tokS[tid] = (b * 56 + sr) * 56 + sc;
    }
    for (int i = tid; i < 338; i += 256) {
        int hh = (i >= 169) ? 1 : 0;
        biasP[i] = table[(i - 169 * hh) * 12 + 2 * hp + hh];
    }
    __syncthreads();

    // ---- cp.async stage: 49 tokens x 3 (q,k,v) x (hi,lo) x 8 chunks ----
    for (int i = tid; i < 2352; i += 256) {
        int t = i / 48;
        int r = i - t * 48;
        int s = r >> 4;
        int q = r & 15;
        int half = q >> 3;
        int c8 = q & 7;
        const unsigned short* src = (half ? qlo : qhi)
            + (size_t)tokS[t] * 1152 + s * 384 + hp * 64 + c8 * 8;
        uint32_t dst = sb + (uint32_t)(((s * 2 + half) * T2_US
                        + t * 72 + c8 * 8) * 2);
        CPA16(dst, src);
    }
    CPA_COMMIT();
    CPA_WAIT0();
    __syncthreads();

    for (int h = 0; h < 2; ++h) {
        // ================= QK^T ================
        {
            uint32_t qh[2][4], ql[2][4];
            #pragma unroll
            for (int ks = 0; ks < 2; ++ks) {
                uint32_t base = (uint32_t)((mt * 16) * 144
                                + (h * 32 + ks * 16) * 2);
                LDM4(qh[ks][0], qh[ks][1], qh[ks][2], qh[ks][3],
                     sb + K2_QH * 2 + base + aoff);
                LDM4(ql[ks][0], ql[ks][1], ql[ks][2], ql[ks][3],
                     sb + K2_QL * 2 + base + aoff);
            }
            float c[4][4];
            #pragma unroll
            for (int nt = 0; nt < 4; ++nt)
                #pragma unroll
                for (int i = 0; i < 4; ++i) c[nt][i] = 0.f;

            #pragma unroll
            for (int ks = 0; ks < 2; ++ks) {
                uint32_t kh[4][2], kl[4][2];
                #pragma unroll
                for (int lp = 0; lp < 2; ++lp) {
                    int ntp = nh * 2 + lp;
                    uint32_t base = (uint32_t)((ntp * 16) * 144
                                    + (h * 32 + ks * 16) * 2);
                    LDM4(kh[2*lp][0], kh[2*lp][1], kh[2*lp+1][0], kh[2*lp+1][1],
                         sb + K2_KH * 2 + base + boff);
                    LDM4(kl[2*lp][0], kl[2*lp][1], kl[2*lp+1][0], kl[2*lp+1][1],
                         sb + K2_KL * 2 + base + boff);
                }
                #pragma unroll
                for (int nt = 0; nt < 4; ++nt) {
                    MMA_BF16(c[nt], qh[ks], kh[nt]);
                    MMA_BF16(c[nt], qh[ks], kl[nt]);
                    MMA_BF16(c[nt], ql[ks], kh[nt]);
                }
            }
            #pragma unroll
            for (int nt = 0; nt < 4; ++nt) {
                int gnt = nh * 4 + nt;
                if (gnt == 7) continue;
                int row = mt * 16 + (lane >> 2);
                int col = gnt * 8 + (lane & 3) * 2;
                *(float2*)(attnS + row * 58 + col) =
                    make_float2(c[nt][0], c[nt][1]);
                *(float2*)(attnS + (row + 8) * 58 + col) =
                    make_float2(c[nt][2], c[nt][3]);
            }
        }
        __syncthreads();

        // ================= softmax -> P hi/lo ==============
        for (int row = wid; row < 49; row += 8) {
            const float* ap = attnS + row * 58;
            int ri = rowS[row], ci = colS[row], rg = regS[row];
            float v0, v1;
            {
                int j = lane;
                if (j < 49) {
                    int rel = (ri - rowS[j] + 6) * 13 + (ci - colS[j] + 6);
                    v0 = ap[j] + biasP[h * 169 + rel];
                    if (rg != regS[j]) v0 -= 100.0f;
                } else v0 = -3.0e38f;
            }
            {
                int j = 32 + lane;
                if (j < 49) {
                    int rel = (ri - rowS[j] + 6) * 13 + (ci - colS[j] + 6);
                    v1 = ap[j] + biasP[h * 169 + rel];
                    if (rg != regS[j]) v1 -= 100.0f;
                } else v1 = -3.0e38f;
            }
            float m = fmaxf(v0, v1);
            #pragma unroll
            for (int off = 16; off; off >>= 1)
                m = fmaxf(m, __shfl_xor_sync(0xffffffffu, m, off));
            float e0 = (lane < 49) ? __expf(v0 - m) : 0.f;
            float e1 = (32 + lane < 49) ? __expf(v1 - m) : 0.f;
            float s = e0 + e1;
            #pragma unroll
            for (int off = 16; off; off >>= 1)
                s += __shfl_xor_sync(0xffffffffu, s, off);
            float inv = 1.0f / s;
            unsigned short ph, pl;
            cvt_split(e0 * inv, ph, pl);
            su[K2_PH + row * 72 + lane] = ph;
            su[K2_PL + row * 72 + lane] = pl;
            if (32 + lane < 49) {
                cvt_split(e1 * inv, ph, pl);
                su[K2_PH + row * 72 + 32 + lane] = ph;
                su[K2_PL + row * 72 + 32 + lane] = pl;
            }
        }
        __syncthreads();

        // ================= out = P @ V ==============
        {
            float c2[2][4];
            #pragma unroll
            for (int dt = 0; dt < 2; ++dt)
                #pragma unroll
                for (int i = 0; i < 4; ++i) c2[dt][i] = 0.f;

            const uint32_t vlo =
                (uint32_t)((((lq & 1) * 8 + lr) * 144)
                           + ((h * 32 + nh * 16 + (lq >> 1) * 8) * 2));

            #pragma unroll
            for (int ks = 0; ks < 4; ++ks) {
                uint32_t aPh[4], aPl[4];
                uint32_t base = (uint32_t)((mt * 16) * 144 + ks * 32);
                LDM4(aPh[0], aPh[1], aPh[2], aPh[3],
                     sb + K2_PH * 2 + base + aoff);
                LDM4(aPl[0], aPl[1], aPl[2], aPl[3],
                     sb + K2_PL * 2 + base + aoff);

                uint32_t vh[2][2], vl[2][2];
                uint32_t vbase = (uint32_t)((16 * ks) * 144);
                LDM4T(vh[0][0], vh[0][1], vh[1][0], vh[1][1],
                      sb + K2_VH * 2 + vbase + vlo);
                LDM4T(vl[0][0], vl[0][1], vl[1][0], vl[1][1],
                      sb + K2_VL * 2 + vbase + vlo);

                #pragma unroll
                for (int dt = 0; dt < 2; ++dt) {
                    MMA_BF16(c2[dt], aPh, vh[dt]);
                    MMA_BF16(c2[dt], aPh, vl[dt]);
                    MMA_BF16(c2[dt], aPl, vh[dt]);
                }
            }
            #pragma unroll
            for (int dt = 0; dt < 2; ++dt) {
                int r0 = mt * 16 + (lane >> 2);
                int col = (2 * hp + h) * 32 + (nh * 2 + dt) * 8
                          + (lane & 3) * 2;
                if (r0 < 49) {
                    unsigned short hx, lx, hy, ly;
                    cvt_split(c2[dt][0], hx, lx);
                    cvt_split(c2[dt][1], hy, ly);
                    size_t o = (size_t)tokS[r0] * 384 + col;
                    *(ushort2*)(ahi + o) = make_ushort2(hx, hy);
                    *(ushort2*)(alo + o) = make_ushort2(lx, ly);
                }
                int r1 = r0 + 8;
                if (r1 < 49) {
                    unsigned short hx, lx, hy, ly;
                    cvt_split(c2[dt][2], hx, lx);
                    cvt_split(c2[dt][3], hy, ly);
                    size_t o = (size_t)tokS[r1] * 384 + col;
                    *(ushort2*)(ahi + o) = make_ushort2(hx, hy);
                    *(ushort2*)(alo + o) = make_ushort2(lx, ly);
                }
            }
        }
        if (h == 0) __syncthreads();
    }
}

// ============================================================================
extern "C" void kernel_launch(void* const* d_in, const int* in_sizes, int n_in,
                              void* d_out, int out_size)
{
    const float* x     = (const float*)d_in[0];
    const float* qkvw  = (const float*)d_in[1];
    const float* qkvb  = (const float*)d_in[2];
    const float* projw = (const float*)d_in[3];
    const float* projb = (const float*)d_in[4];
    const float* table = (const float*)d_in[5];
    float* out = (float*)d_out;

    unsigned short *qhi, *qlo, *xhi, *xlo, *ahi, *alo, *whi, *wlo, *phi, *plo;
    cudaGetSymbolAddress((void**)&qhi, g_qhi);
    cudaGetSymbolAddress((void**)&qlo, g_qlo);
    cudaGetSymbolAddress((void**)&xhi, g_xhi);
    cudaGetSymbolAddress((void**)&xlo, g_xlo);
    cudaGetSymbolAddress((void**)&ahi, g_ahi);
    cudaGetSymbolAddress((void**)&alo, g_alo);
    cudaGetSymbolAddress((void**)&whi, g_whi);
    cudaGetSymbolAddress((void**)&wlo, g_wlo);
    cudaGetSymbolAddress((void**)&phi, g_phi);
    cudaGetSymbolAddress((void**)&plo, g_plo);

    cudaFuncSetAttribute(gemm_bf16x3_kernel,
                         cudaFuncAttributeMaxDynamicSharedMemorySize, GSMEM_BYTES);
    cudaFuncSetAttribute(swin_attn_mma_kernel,
                         cudaFuncAttributeMaxDynamicSharedMemorySize, K2_SMEM_BYTES);

    split_bf16_kernel<<<18816, 256>>>((const float4*)x, (ushort4*)xhi,
                                      (ushort4*)xlo, 4816896);
    split_bf16_kernel<<<432, 256>>>((const float4*)qkvw, (ushort4*)whi,
                                    (ushort4*)wlo, 110592);
    split_bf16_kernel<<<144, 256>>>((const float4*)projw, (ushort4*)phi,
                                    (ushort4*)plo, 36864);

    gemm_bf16x3_kernel<<<dim3(392, 9), 256, GSMEM_BYTES>>>(
        xhi, xlo, whi, wlo, qkvb, nullptr, qhi, qlo, 1152, 1);
    swin_attn_mma_kernel<<<dim3(1024, 6), 256, K2_SMEM_BYTES>>>(
        qhi, qlo, table, ahi, alo);
    gemm_bf16x3_kernel<<<dim3(392, 3), 256, GSMEM_BYTES>>>(
        ahi, alo, phi, plo, projb, out, nullptr, nullptr, 384, 0);
}

// round 14
// speedup vs baseline: 1.5116x; 1.5116x over previous
#include <cuda_runtime.h>
#include <cuda_bf16.h>
#include <cstdint>

// ============================================================================
// Shifted-window attention pipeline:
//   K0: split X / qkvw / projw into bf16 (hi, lo) pairs        (elementwise)
//   K1: qkv(hi,lo) = X @ qkvw^T + qkvb   (bf16 3-term MMA, 128x128 tile,
//        K-chunk 32, 2-stage cp.async(.cg), 2 CTAs/SM)
//   K2: per-(window, head-pair) attention via mma.sync, grid (1024, 6)
//   K3: out = attno @ projw^T + projb    (same GEMM, fp32 out)
// ============================================================================

#define KDIM 384
#define NTOKENS 50176   // 16*56*56 = 392*128

static __device__ unsigned short g_qhi[(size_t)NTOKENS * 1152];
static __device__ unsigned short g_qlo[(size_t)NTOKENS * 1152];
static __device__ unsigned short g_xhi[(size_t)NTOKENS * 384];
static __device__ unsigned short g_xlo[(size_t)NTOKENS * 384];
static __device__ unsigned short g_ahi[(size_t)NTOKENS * 384];
static __device__ unsigned short g_alo[(size_t)NTOKENS * 384];
static __device__ unsigned short g_whi[1152 * 384];
static __device__ unsigned short g_wlo[1152 * 384];
static __device__ unsigned short g_phi[384 * 384];
static __device__ unsigned short g_plo[384 * 384];

__device__ __forceinline__ uint32_t smem_u32(const void* p) {
    uint32_t a;
    asm("{ .reg .u64 t; cvta.to.shared.u64 t, %1; cvt.u32.u64 %0, t; }"
        : "=r"(a) : "l"(p));
    return a;
}
#define LDM4(r0, r1, r2, r3, addr)                                           \
    asm volatile("ldmatrix.sync.aligned.m8n8.x4.shared.b16 {%0,%1,%2,%3}, [%4];" \
                 : "=r"(r0), "=r"(r1), "=r"(r2), "=r"(r3) : "r"(addr))
#define LDM4T(r0, r1, r2, r3, addr)                                          \
    asm volatile("ldmatrix.sync.aligned.m8n8.x4.trans.shared.b16 {%0,%1,%2,%3}, [%4];" \
                 : "=r"(r0), "=r"(r1), "=r"(r2), "=r"(r3) : "r"(addr))
#define MMA_BF16(c, a, b)                                                    \
    asm volatile("mma.sync.aligned.m16n8k16.row.col.f32.bf16.bf16.f32 "      \
                 "{%0,%1,%2,%3}, {%4,%5,%6,%7}, {%8,%9}, {%0,%1,%2,%3};"     \
                 : "+f"((c)[0]), "+f"((c)[1]), "+f"((c)[2]), "+f"((c)[3])    \
                 : "r"((a)[0]), "r"((a)[1]), "r"((a)[2]), "r"((a)[3]),       \
                   "r"((b)[0]), "r"((b)[1]))
#define CPA16(dst, src)                                                      \
    asm volatile("cp.async.cg.shared.global [%0], [%1], 16;" :: "r"(dst), "l"(src))
#define CPA_COMMIT() asm volatile("cp.async.commit_group;")
#define CPA_WAIT1()  asm volatile("cp.async.wait_group 1;")
#define CPA_WAIT0()  asm volatile("cp.async.wait_group 0;")

__device__ __forceinline__ void cvt_split(float x, unsigned short& h,
                                          unsigned short& l) {
    __nv_bfloat16 bh = __float2bfloat16_rn(x);
    h = __bfloat16_as_ushort(bh);
    l = __bfloat16_as_ushort(__float2bfloat16_rn(x - __bfloat162float(bh)));
}

// ============================================================================
// K0: fp32 -> bf16 hi/lo split
// ============================================================================
__global__ void __launch_bounds__(256)
split_bf16_kernel(const float4* __restrict__ in, ushort4* __restrict__ hi,
                  ushort4* __restrict__ lo, int n4)
{
    int i = blockIdx.x * 256 + threadIdx.x;
    if (i >= n4) return;
    float4 v = in[i];
    ushort4 h, l;
    cvt_split(v.x, h.x, l.x);
    cvt_split(v.y, h.y, l.y);
    cvt_split(v.z, h.z, l.z);
    cvt_split(v.w, h.w, l.w);
    hi[i] = h;
    lo[i] = l;
}

// ============================================================================
// K1/K3 GEMM (R12-proven: 128x128 tile, K-chunk 32, 2 CTAs/SM)
// ============================================================================
#define GSTR 40
#define TILE_US (128 * GSTR)            // 5120
#define STAGE_US (4 * TILE_US)          // 20480
#define GSMEM_BYTES (2 * STAGE_US * 2)  // 81920

__global__ void __launch_bounds__(256, 2)
gemm_bf16x3_kernel(const unsigned short* __restrict__ Ahi_g,
                   const unsigned short* __restrict__ Alo_g,
                   const unsigned short* __restrict__ Bhi_g,
                   const unsigned short* __restrict__ Blo_g,
                   const float* __restrict__ bias, float* __restrict__ C,
                   unsigned short* __restrict__ Chi,
                   unsigned short* __restrict__ Clo,
                   int ncols, int qflag)
{
    extern __shared__ __align__(16) unsigned short gsm[];

    const int tid  = threadIdx.x;
    const int lane = tid & 31;
    const int wid  = tid >> 5;
    const int wm   = wid & 3;
    const int wn   = wid >> 2;
    const int mbase = blockIdx.x * 128;
    const int nbase = blockIdx.y * 128;
    const uint32_t sbase = smem_u32(gsm);

    const int lr = lane & 7, lq = lane >> 3;
    const uint32_t aoff =
        (uint32_t)((((lq & 1) * 8 + lr) * GSTR + (lq >> 1) * 8) * 2);
    const uint32_t boff =
        (uint32_t)((((lq >> 1) * 8 + lr) * GSTR + (lq & 1) * 8) * 2);

    float c[2][8][4];
    #pragma unroll
    for (int mt = 0; mt < 2; ++mt)
        #pragma unroll
        for (int nt = 0; nt < 8; ++nt)
            #pragma unroll
            for (int i = 0; i < 4; ++i) c[mt][nt][i] = 0.f;

    auto prefetch = [&](int sbuf, int kc) {
        const uint32_t st = sbase + (uint32_t)sbuf * (STAGE_US * 2);
        #pragma unroll
        for (int j = 0; j < 8; ++j) {
            int cch = tid + 256 * j;
            int tile = cch >> 9;
            int rc = cch & 511;
            int row = rc >> 2, c8 = rc & 3;
            uint32_t doff = (uint32_t)(tile * (TILE_US * 2) + row * 80 + c8 * 16);
            const unsigned short* srcb;
            size_t idx;
            if (tile < 2) {
                srcb = (tile & 1) ? Alo_g : Ahi_g;
                idx = (size_t)(mbase + row) * KDIM + kc * 32 + c8 * 8;
            } else {
                srcb = (tile & 1) ? Blo_g : Bhi_g;
                idx = (size_t)(nbase + row) * KDIM + kc * 32 + c8 * 8;
            }
            CPA16(st + doff, srcb + idx);
        }
        CPA_COMMIT();
    };

    prefetch(0, 0);

    for (int kc = 0; kc < 12; ++kc) {
        if (kc + 1 < 12) {
            prefetch((kc + 1) & 1, kc + 1);
            CPA_WAIT1();
        } else {
            CPA_WAIT0();
        }
        __syncthreads();

        const uint32_t st = sbase + (uint32_t)(kc & 1) * (STAGE_US * 2);
        const uint32_t sAhi = st;
        const uint32_t sAlo = st + TILE_US * 2;
        const uint32_t sBhi = st + 2 * TILE_US * 2;
        const uint32_t sBlo = st + 3 * TILE_US * 2;

        #pragma unroll
        for (int ks = 0; ks < 2; ++ks) {
            const uint32_t kb = (uint32_t)(ks * 32);
            uint32_t ah[2][4], al[2][4];
            #pragma unroll
            for (int mt = 0; mt < 2; ++mt) {
                uint32_t base = (uint32_t)((wm * 32 + mt * 16) * (GSTR * 2)) + kb;
                LDM4(ah[mt][0], ah[mt][1], ah[mt][2], ah[mt][3], sAhi + base + aoff);
                LDM4(al[mt][0], al[mt][1], al[mt][2], al[mt][3], sAlo + base + aoff);
            }
            #pragma unroll
            for (int ntp = 0; ntp < 4; ++ntp) {
                uint32_t bh[2][2], bl[2][2];
                uint32_t base = (uint32_t)((wn * 64 + ntp * 16) * (GSTR * 2)) + kb;
                LDM4(bh[0][0], bh[0][1], bh[1][0], bh[1][1], sBhi + base + boff);
                LDM4(bl[0][0], bl[0][1], bl[1][0], bl[1][1], sBlo + base + boff);
                #pragma unroll
                for (int mt = 0; mt < 2; ++mt)
                    #pragma unroll
                    for (int j = 0; j < 2; ++j) {
                        MMA_BF16(c[mt][ntp * 2 + j], ah[mt], bh[j]);
                        MMA_BF16(c[mt][ntp * 2 + j], ah[mt], bl[j]);
                        MMA_BF16(c[mt][ntp * 2 + j], al[mt], bh[j]);
                    }
            }
        }
        __syncthreads();
    }

    const float qscale = 0.17677669529663687f;
    #pragma unroll
    for (int mt = 0; mt < 2; ++mt) {
        #pragma unroll
        for (int nt = 0; nt < 8; ++nt) {
            int row0 = mbase + wm * 32 + mt * 16 + (lane >> 2);
            int col  = nbase + wn * 64 + nt * 8 + (lane & 3) * 2;
            float sc = (qflag && col < 384) ? qscale : 1.0f;
            float b0 = __ldg(bias + col), b1 = __ldg(bias + col + 1);
            float v00 = (c[mt][nt][0] + b0) * sc;
            float v01 = (c[mt][nt][1] + b1) * sc;
            float v10 = (c[mt][nt][2] + b0) * sc;
            float v11 = (c[mt][nt][3] + b1) * sc;
            if (Chi != nullptr) {
                unsigned short h0, l0, h1, l1;
                cvt_split(v00, h0, l0); cvt_split(v01, h1, l1);
                *(ushort2*)(Chi + (size_t)row0 * ncols + col) = make_ushort2(h0, h1);
                *(ushort2*)(Clo + (size_t)row0 * ncols + col) = make_ushort2(l0, l1);
                cvt_split(v10, h0, l0); cvt_split(v11, h1, l1);
                *(ushort2*)(Chi + (size_t)(row0 + 8) * ncols + col) = make_ushort2(h0, h1);
                *(ushort2*)(Clo + (size_t)(row0 + 8) * ncols + col) = make_ushort2(l0, l1);
            } else {
                *(float2*)(C + (size_t)row0 * ncols + col) = make_float2(v00, v01);
                *(float2*)(C + (size_t)(row0 + 8) * ncols + col) = make_float2(v10, v11);
            }
        }
    }
}

// ============================================================================
// K2: attention, one CTA per (window, head-pair). grid (1024, 6).
// ============================================================================
#define T2_US 4608            // 64*72
#define K2_QH 0
#define K2_QL (1*T2_US)
#define K2_KH (2*T2_US)
#define K2_KL (3*T2_US)
#define K2_VH (4*T2_US)
#define K2_VL (5*T2_US)
#define K2_PH (6*T2_US)
#define K2_PL (7*T2_US)
#define K2_ATT_F 18432
#define K2_BIAS_F (K2_ATT_F + 3712)
#define K2_INTS_F (K2_BIAS_F + 338)
#define K2_SMEM_BYTES 90752

__global__ void __launch_bounds__(256, 2)
swin_attn_mma_kernel(const unsigned short* __restrict__ qhi,
                     const unsigned short* __restrict__ qlo,
                     const float* __restrict__ table,
                     unsigned short* __restrict__ ahi,
                     unsigned short* __restrict__ alo)
{
    extern __shared__ float sf[];
    unsigned short* su = (unsigned short*)sf;
    float* attnS = sf + K2_ATT_F;          // [64][58]
    float* biasP = sf + K2_BIAS_F;         // [2][169]
    int*   tokS  = (int*)(sf + K2_INTS_F);
    int*   regS  = tokS + 49;
    int*   rowS  = regS + 49;
    int*   colS  = rowS + 49;

    const int tid  = threadIdx.x;
    const int lane = tid & 31;
    const int wid  = tid >> 5;
    const int mt   = wid & 3;
    const int nh   = wid >> 2;
    const int w    = blockIdx.x;
    const int hp   = blockIdx.y;          // head pair 0..5
    const int b    = w >> 6;
    const int wi   = w & 63;
    const int wr   = wi >> 3;
    const int wc   = wi & 7;

    const uint32_t sb = smem_u32(su);
    const int lr = lane & 7, lq = lane >> 3;
    const uint32_t aoff =
        (uint32_t)((((lq & 1) * 8 + lr) * 72 + (lq >> 1) * 8) * 2);
    const uint32_t boff =
        (uint32_t)((((lq >> 1) * 8 + lr) * 72 + (lq & 1) * 8) * 2);

    {
        unsigned long long* z = (unsigned long long*)su;
        for (int i = tid; i < 8 * T2_US / 4; i += 256) z[i] = 0ull;
    }

    if (tid < 49) {
        int tr = tid / 7, tc = tid - tr * 7;
        rowS[tid] = tr; colS[tid] = tc;
        int gr = wr * 7 + tr, gc = wc * 7 + tc;
        int rh = (gr < 49) ? 0 : (gr < 53 ? 1 : 2);
        int rw = (gc < 49) ? 0 : (gc < 53 ? 1 : 2);
        regS[tid] = rh * 3 + rw;
        int sr = gr + 3; if (sr >= 56) sr -= 56;
        int sc = gc + 3; if (sc >= 56) sc -= 56;
        tokS[tid] = (b * 56 + sr) * 56 + sc;
    }
    for (int i = tid; i < 338; i += 256) {
        int hh = (i >= 169) ? 1 : 0;
        biasP[i] = table[(i - 169 * hh) * 12 + 2 * hp + hh];
    }
    __syncthreads();

    for (int i = tid; i < 2352; i += 256) {
        int t = i / 48;
        int r = i - t * 48;
        int s = r >> 4;
        int q = r & 15;
        int half = q >> 3;
        int c8 = q & 7;
        const unsigned short* src = (half ? qlo : qhi)
            + (size_t)tokS[t] * 1152 + s * 384 + hp * 64 + c8 * 8;
        uint32_t dst = sb + (uint32_t)(((s * 2 + half) * T2_US
                        + t * 72 + c8 * 8) * 2);
        CPA16(dst, src);
    }
    CPA_COMMIT();
    CPA_WAIT0();
    __syncthreads();

    for (int h = 0; h < 2; ++h) {
        // ================= QK^T ================
        {
            uint32_t qh[2][4], ql[2][4];
            #pragma unroll
            for (int ks = 0; ks < 2; ++ks) {
                uint32_t base = (uint32_t)((mt * 16) * 144
                                + (h * 32 + ks * 16) * 2);
                LDM4(qh[ks][0], qh[ks][1], qh[ks][2], qh[ks][3],
                     sb + K2_QH * 2 + base + aoff);
                LDM4(ql[ks][0], ql[ks][1], ql[ks][2], ql[ks][3],
                     sb + K2_QL * 2 + base + aoff);
            }
            float c[4][4];
            #pragma unroll
            for (int nt = 0; nt < 4; ++nt)
                #pragma unroll
                for (int i = 0; i < 4; ++i) c[nt][i] = 0.f;

            #pragma unroll
            for (int ks = 0; ks < 2; ++ks) {
                uint32_t kh[4][2], kl[4][2];
                #pragma unroll
                for (int lp = 0; lp < 2; ++lp) {
                    int ntp = nh * 2 + lp;
                    uint32_t base = (uint32_t)((ntp * 16) * 144
                                    + (h * 32 + ks * 16) * 2);
                    LDM4(kh[2*lp][0], kh[2*lp][1], kh[2*lp+1][0], kh[2*lp+1][1],
                         sb + K2_KH * 2 + base + boff);
                    LDM4(kl[2*lp][0], kl[2*lp][1], kl[2*lp+1][0], kl[2*lp+1][1],
                         sb + K2_KL * 2 + base + boff);
                }
                #pragma unroll
                for (int nt = 0; nt < 4; ++nt) {
                    MMA_BF16(c[nt], qh[ks], kh[nt]);
                    MMA_BF16(c[nt], qh[ks], kl[nt]);
                    MMA_BF16(c[nt], ql[ks], kh[nt]);
                }
            }
            #pragma unroll
            for (int nt = 0; nt < 4; ++nt) {
                int gnt = nh * 4 + nt;
                if (gnt == 7) continue;
                int row = mt * 16 + (lane >> 2);
                int col = gnt * 8 + (lane & 3) * 2;
                *(float2*)(attnS + row * 58 + col) =
                    make_float2(c[nt][0], c[nt][1]);
                *(float2*)(attnS + (row + 8) * 58 + col) =
                    make_float2(c[nt][2], c[nt][3]);
            }
        }
        __syncthreads();

        // ================= softmax -> P hi/lo ==============
        for (int row = wid; row < 49; row += 8) {
            const float* ap = attnS + row * 58;
            int ri = rowS[row], ci = colS[row], rg = regS[row];
            float v0, v1;
            {
                int j = lane;
                if (j < 49) {
                    int rel = (ri - rowS[j] + 6) * 13 + (ci - colS[j] + 6);
                    v0 = ap[j] + biasP[h * 169 + rel];
                    if (rg != regS[j]) v0 -= 100.0f;
                } else v0 = -3.0e38f;
            }
            {
                int j = 32 + lane;
                if (j < 49) {
                    int rel = (ri - rowS[j] + 6) * 13 + (ci - colS[j] + 6);
                    v1 = ap[j] + biasP[h * 169 + rel];
                    if (rg != regS[j]) v1 -= 100.0f;
                } else v1 = -3.0e38f;
            }
            float m = fmaxf(v0, v1);
            #pragma unroll
            for (int off = 16; off; off >>= 1)
                m = fmaxf(m, __shfl_xor_sync(0xffffffffu, m, off));
            float e0 = (lane < 49) ? __expf(v0 - m) : 0.f;
            float e1 = (32 + lane < 49) ? __expf(v1 - m) : 0.f;
            float s = e0 + e1;
            #pragma unroll
            for (int off = 16; off; off >>= 1)
                s += __shfl_xor_sync(0xffffffffu, s, off);
            float inv = 1.0f / s;
            unsigned short ph, pl;
            cvt_split(e0 * inv, ph, pl);
            su[K2_PH + row * 72 + lane] = ph;
            su[K2_PL + row * 72 + lane] = pl;
            if (32 + lane < 49) {
                cvt_split(e1 * inv, ph, pl);
                su[K2_PH + row * 72 + 32 + lane] = ph;
                su[K2_PL + row * 72 + 32 + lane] = pl;
            }
        }
        __syncthreads();

        // ================= out = P @ V ==============
        {
            float c2[2][4];
            #pragma unroll
            for (int dt = 0; dt < 2; ++dt)
                #pragma unroll
                for (int i = 0; i < 4; ++i) c2[dt][i] = 0.f;

            const uint32_t vlo =
                (uint32_t)((((lq & 1) * 8 + lr) * 144)
                           + ((h * 32 + nh * 16 + (lq >> 1) * 8) * 2));

            #pragma unroll
            for (int ks = 0; ks < 4; ++ks) {
                uint32_t aPh[4], aPl[4];
                uint32_t base = (uint32_t)((mt * 16) * 144 + ks * 32);
                LDM4(aPh[0], aPh[1], aPh[2], aPh[3],
                     sb + K2_PH * 2 + base + aoff);
                LDM4(aPl[0], aPl[1], aPl[2], aPl[3],
                     sb + K2_PL * 2 + base + aoff);

                uint32_t vh[2][2], vl[2][2];
                uint32_t vbase = (uint32_t)((16 * ks) * 144);
                LDM4T(vh[0][0], vh[0][1], vh[1][0], vh[1][1],
                      sb + K2_VH * 2 + vbase + vlo);
                LDM4T(vl[0][0], vl[0][1], vl[1][0], vl[1][1],
                      sb + K2_VL * 2 + vbase + vlo);

                #pragma unroll
                for (int dt = 0; dt < 2; ++dt) {
                    MMA_BF16(c2[dt], aPh, vh[dt]);
                    MMA_BF16(c2[dt], aPh, vl[dt]);
                    MMA_BF16(c2[dt], aPl, vh[dt]);
                }
            }
            #pragma unroll
            for (int dt = 0; dt < 2; ++dt) {
                int r0 = mt * 16 + (lane >> 2);
                int col = (2 * hp + h) * 32 + (nh * 2 + dt) * 8
                          + (lane & 3) * 2;
                if (r0 < 49) {
                    unsigned short hx, lx, hy, ly;
                    cvt_split(c2[dt][0], hx, lx);
                    cvt_split(c2[dt][1], hy, ly);
                    size_t o = (size_t)tokS[r0] * 384 + col;
                    *(ushort2*)(ahi + o) = make_ushort2(hx, hy);
                    *(ushort2*)(alo + o) = make_ushort2(lx, ly);
                }
                int r1 = r0 + 8;
                if (r1 < 49) {
                    unsigned short hx, lx, hy, ly;
                    cvt_split(c2[dt][2], hx, lx);
                    cvt_split(c2[dt][3], hy, ly);
                    size_t o = (size_t)tokS[r1] * 384 + col;
                    *(ushort2*)(ahi + o) = make_ushort2(hx, hy);
                    *(ushort2*)(alo + o) = make_ushort2(lx, ly);
                }
            }
        }
        if (h == 0) __syncthreads();
    }
}

// ============================================================================
extern "C" void kernel_launch(void* const* d_in, const int* in_sizes, int n_in,
                              void* d_out, int out_size)
{
    const float* x     = (const float*)d_in[0];
    const float* qkvw  = (const float*)d_in[1];
    const float* qkvb  = (const float*)d_in[2];
    const float* projw = (const float*)d_in[3];
    const float* projb = (const float*)d_in[4];
    const float* table = (const float*)d_in[5];
    float* out = (float*)d_out;

    unsigned short *qhi, *qlo, *xhi, *xlo, *ahi, *alo, *whi, *wlo, *phi, *plo;
    cudaGetSymbolAddress((void**)&qhi, g_qhi);
    cudaGetSymbolAddress((void**)&qlo, g_qlo);
    cudaGetSymbolAddress((void**)&xhi, g_xhi);
    cudaGetSymbolAddress((void**)&xlo, g_xlo);
    cudaGetSymbolAddress((void**)&ahi, g_ahi);
    cudaGetSymbolAddress((void**)&alo, g_alo);
    cudaGetSymbolAddress((void**)&whi, g_whi);
    cudaGetSymbolAddress((void**)&wlo, g_wlo);
    cudaGetSymbolAddress((void**)&phi, g_phi);
    cudaGetSymbolAddress((void**)&plo, g_plo);

    cudaFuncSetAttribute(gemm_bf16x3_kernel,
                         cudaFuncAttributeMaxDynamicSharedMemorySize, GSMEM_BYTES);
    cudaFuncSetAttribute(swin_attn_mma_kernel,
                         cudaFuncAttributeMaxDynamicSharedMemorySize, K2_SMEM_BYTES);

    split_bf16_kernel<<<18816, 256>>>((const float4*)x, (ushort4*)xhi,
                                      (ushort4*)xlo, 4816896);
    split_bf16_kernel<<<432, 256>>>((const float4*)qkvw, (ushort4*)whi,
                                    (ushort4*)wlo, 110592);
    split_bf16_kernel<<<144, 256>>>((const float4*)projw, (ushort4*)phi,
                                    (ushort4*)plo, 36864);

    gemm_bf16x3_kernel<<<dim3(392, 9), 256, GSMEM_BYTES>>>(
        xhi, xlo, whi, wlo, qkvb, nullptr, qhi, qlo, 1152, 1);
    swin_attn_mma_kernel<<<dim3(1024, 6), 256, K2_SMEM_BYTES>>>(
        qhi, qlo, table, ahi, alo);
    gemm_bf16x3_kernel<<<dim3(392, 3), 256, GSMEM_BYTES>>>(
        ahi, alo, phi, plo, projb, out, nullptr, nullptr, 384, 0);
}

// round 15
// speedup vs baseline: 1.5402x; 1.0190x over previous
#include <cuda_runtime.h>
#include <cuda_bf16.h>
#include <cstdint>

// ============================================================================
// Shifted-window attention pipeline:
//   K0: split X / qkvw / projw into bf16 (hi, lo) pairs        (elementwise)
//   K1: qkv(hi,lo) = X @ qkvw^T + qkvb   (bf16 3-term MMA, 128x128 tile,
//        K-chunk 32, 2-stage cp.async(.cg), single-barrier pipeline,
//        2 CTAs/SM)
//   K2: per-(window, head-pair) attention via mma.sync, grid (1024, 6)
//   K3: out = attno @ projw^T + projb    (same GEMM, fp32 out)
// ============================================================================

#define KDIM 384
#define NTOKENS 50176   // 16*56*56 = 392*128

static __device__ unsigned short g_qhi[(size_t)NTOKENS * 1152];
static __device__ unsigned short g_qlo[(size_t)NTOKENS * 1152];
static __device__ unsigned short g_xhi[(size_t)NTOKENS * 384];
static __device__ unsigned short g_xlo[(size_t)NTOKENS * 384];
static __device__ unsigned short g_ahi[(size_t)NTOKENS * 384];
static __device__ unsigned short g_alo[(size_t)NTOKENS * 384];
static __device__ unsigned short g_whi[1152 * 384];
static __device__ unsigned short g_wlo[1152 * 384];
static __device__ unsigned short g_phi[384 * 384];
static __device__ unsigned short g_plo[384 * 384];

__device__ __forceinline__ uint32_t smem_u32(const void* p) {
    uint32_t a;
    asm("{ .reg .u64 t; cvta.to.shared.u64 t, %1; cvt.u32.u64 %0, t; }"
        : "=r"(a) : "l"(p));
    return a;
}
#define LDM4(r0, r1, r2, r3, addr)                                           \
    asm volatile("ldmatrix.sync.aligned.m8n8.x4.shared.b16 {%0,%1,%2,%3}, [%4];" \
                 : "=r"(r0), "=r"(r1), "=r"(r2), "=r"(r3) : "r"(addr))
#define LDM4T(r0, r1, r2, r3, addr)                                          \
    asm volatile("ldmatrix.sync.aligned.m8n8.x4.trans.shared.b16 {%0,%1,%2,%3}, [%4];" \
                 : "=r"(r0), "=r"(r1), "=r"(r2), "=r"(r3) : "r"(addr))
#define MMA_BF16(c, a, b)                                                    \
    asm volatile("mma.sync.aligned.m16n8k16.row.col.f32.bf16.bf16.f32 "      \
                 "{%0,%1,%2,%3}, {%4,%5,%6,%7}, {%8,%9}, {%0,%1,%2,%3};"     \
                 : "+f"((c)[0]), "+f"((c)[1]), "+f"((c)[2]), "+f"((c)[3])    \
                 : "r"((a)[0]), "r"((a)[1]), "r"((a)[2]), "r"((a)[3]),       \
                   "r"((b)[0]), "r"((b)[1]))
#define CPA16(dst, src)                                                      \
    asm volatile("cp.async.cg.shared.global [%0], [%1], 16;" :: "r"(dst), "l"(src))
#define CPA_COMMIT() asm volatile("cp.async.commit_group;")
#define CPA_WAIT0()  asm volatile("cp.async.wait_group 0;")

__device__ __forceinline__ void cvt_split(float x, unsigned short& h,
                                          unsigned short& l) {
    __nv_bfloat16 bh = __float2bfloat16_rn(x);
    h = __bfloat16_as_ushort(bh);
    l = __bfloat16_as_ushort(__float2bfloat16_rn(x - __bfloat162float(bh)));
}

// ============================================================================
// K0: fp32 -> bf16 hi/lo split
// ============================================================================
__global__ void __launch_bounds__(256)
split_bf16_kernel(const float4* __restrict__ in, ushort4* __restrict__ hi,
                  ushort4* __restrict__ lo, int n4)
{
    int i = blockIdx.x * 256 + threadIdx.x;
    if (i >= n4) return;
    float4 v = in[i];
    ushort4 h, l;
    cvt_split(v.x, h.x, l.x);
    cvt_split(v.y, h.y, l.y);
    cvt_split(v.z, h.z, l.z);
    cvt_split(v.w, h.w, l.w);
    hi[i] = h;
    lo[i] = l;
}

// ============================================================================
// K1/K3 GEMM: 128x128 tile, K-chunk 32, 2-stage cp.async, 2 CTAs/SM.
// Pipeline: wait0 -> sync -> prefetch(kc+1) -> compute(kc)  (ONE barrier).
// Safety: the sync makes stage kc CTA-visible AND guarantees all warps are
// past compute(kc-1), so prefetch into buffer (kc+1)&1 (read at kc-1) races
// with nothing. Prefetch overlaps all of compute(kc).
// ============================================================================
#define GSTR 40
#define TILE_US (128 * GSTR)            // 5120
#define STAGE_US (4 * TILE_US)          // 20480
#define GSMEM_BYTES (2 * STAGE_US * 2)  // 81920

__global__ void __launch_bounds__(256, 2)
gemm_bf16x3_kernel(const unsigned short* __restrict__ Ahi_g,
                   const unsigned short* __restrict__ Alo_g,
                   const unsigned short* __restrict__ Bhi_g,
                   const unsigned short* __restrict__ Blo_g,
                   const float* __restrict__ bias, float* __restrict__ C,
                   unsigned short* __restrict__ Chi,
                   unsigned short* __restrict__ Clo,
                   int ncols, int qflag)
{
    extern __shared__ __align__(16) unsigned short gsm[];

    const int tid  = threadIdx.x;
    const int lane = tid & 31;
    const int wid  = tid >> 5;
    const int wm   = wid & 3;
    const int wn   = wid >> 2;
    const int mbase = blockIdx.x * 128;
    const int nbase = blockIdx.y * 128;
    const uint32_t sbase = smem_u32(gsm);

    const int lr = lane & 7, lq = lane >> 3;
    const uint32_t aoff =
        (uint32_t)((((lq & 1) * 8 + lr) * GSTR + (lq >> 1) * 8) * 2);
    const uint32_t boff =
        (uint32_t)((((lq >> 1) * 8 + lr) * GSTR + (lq & 1) * 8) * 2);

    float c[2][8][4];
    #pragma unroll
    for (int mt = 0; mt < 2; ++mt)
        #pragma unroll
        for (int nt = 0; nt < 8; ++nt)
            #pragma unroll
            for (int i = 0; i < 4; ++i) c[mt][nt][i] = 0.f;

    auto prefetch = [&](int sbuf, int kc) {
        const uint32_t st = sbase + (uint32_t)sbuf * (STAGE_US * 2);
        #pragma unroll
        for (int j = 0; j < 8; ++j) {
            int cch = tid + 256 * j;
            int tile = cch >> 9;
            int rc = cch & 511;
            int row = rc >> 2, c8 = rc & 3;
            uint32_t doff = (uint32_t)(tile * (TILE_US * 2) + row * 80 + c8 * 16);
            const unsigned short* srcb;
            size_t idx;
            if (tile < 2) {
                srcb = (tile & 1) ? Alo_g : Ahi_g;
                idx = (size_t)(mbase + row) * KDIM + kc * 32 + c8 * 8;
            } else {
                srcb = (tile & 1) ? Blo_g : Bhi_g;
                idx = (size_t)(nbase + row) * KDIM + kc * 32 + c8 * 8;
            }
            CPA16(st + doff, srcb + idx);
        }
        CPA_COMMIT();
    };

    prefetch(0, 0);

    for (int kc = 0; kc < 12; ++kc) {
        CPA_WAIT0();          // stage kc resident (this thread)
        __syncthreads();      // CTA-visible; all warps past compute(kc-1)
        if (kc + 1 < 12) prefetch((kc + 1) & 1, kc + 1);

        const uint32_t st = sbase + (uint32_t)(kc & 1) * (STAGE_US * 2);
        const uint32_t sAhi = st;
        const uint32_t sAlo = st + TILE_US * 2;
        const uint32_t sBhi = st + 2 * TILE_US * 2;
        const uint32_t sBlo = st + 3 * TILE_US * 2;

        #pragma unroll
        for (int ks = 0; ks < 2; ++ks) {
            const uint32_t kb = (uint32_t)(ks * 32);
            uint32_t ah[2][4], al[2][4];
            #pragma unroll
            for (int mt = 0; mt < 2; ++mt) {
                uint32_t base = (uint32_t)((wm * 32 + mt * 16) * (GSTR * 2)) + kb;
                LDM4(ah[mt][0], ah[mt][1], ah[mt][2], ah[mt][3], sAhi + base + aoff);
                LDM4(al[mt][0], al[mt][1], al[mt][2], al[mt][3], sAlo + base + aoff);
            }
            #pragma unroll
            for (int ntp = 0; ntp < 4; ++ntp) {
                uint32_t bh[2][2], bl[2][2];
                uint32_t base = (uint32_t)((wn * 64 + ntp * 16) * (GSTR * 2)) + kb;
                LDM4(bh[0][0], bh[0][1], bh[1][0], bh[1][1], sBhi + base + boff);
                LDM4(bl[0][0], bl[0][1], bl[1][0], bl[1][1], sBlo + base + boff);
                #pragma unroll
                for (int mt = 0; mt < 2; ++mt)
                    #pragma unroll
                    for (int j = 0; j < 2; ++j) {
                        MMA_BF16(c[mt][ntp * 2 + j], ah[mt], bh[j]);
                        MMA_BF16(c[mt][ntp * 2 + j], ah[mt], bl[j]);
                        MMA_BF16(c[mt][ntp * 2 + j], al[mt], bh[j]);
                    }
            }
        }
    }

    const float qscale = 0.17677669529663687f;
    #pragma unroll
    for (int mt = 0; mt < 2; ++mt) {
        #pragma unroll
        for (int nt = 0; nt < 8; ++nt) {
            int row0 = mbase + wm * 32 + mt * 16 + (lane >> 2);
            int col  = nbase + wn * 64 + nt * 8 + (lane & 3) * 2;
            float sc = (qflag && col < 384) ? qscale : 1.0f;
            float b0 = __ldg(bias + col), b1 = __ldg(bias + col + 1);
            float v00 = (c[mt][nt][0] + b0) * sc;
            float v01 = (c[mt][nt][1] + b1) * sc;
            float v10 = (c[mt][nt][2] + b0) * sc;
            float v11 = (c[mt][nt][3] + b1) * sc;
            if (Chi != nullptr) {
                unsigned short h0, l0, h1, l1;
                cvt_split(v00, h0, l0); cvt_split(v01, h1, l1);
                *(ushort2*)(Chi + (size_t)row0 * ncols + col) = make_ushort2(h0, h1);
                *(ushort2*)(Clo + (size_t)row0 * ncols + col) = make_ushort2(l0, l1);
                cvt_split(v10, h0, l0); cvt_split(v11, h1, l1);
                *(ushort2*)(Chi + (size_t)(row0 + 8) * ncols + col) = make_ushort2(h0, h1);
                *(ushort2*)(Clo + (size_t)(row0 + 8) * ncols + col) = make_ushort2(l0, l1);
            } else {
                *(float2*)(C + (size_t)row0 * ncols + col) = make_float2(v00, v01);
                *(float2*)(C + (size_t)(row0 + 8) * ncols + col) = make_float2(v10, v11);
            }
        }
    }
}

// ============================================================================
// K2: attention, one CTA per (window, head-pair). grid (1024, 6).
// (unchanged from R14)
// ============================================================================
#define T2_US 4608            // 64*72
#define K2_QH 0
#define K2_QL (1*T2_US)
#define K2_KH (2*T2_US)
#define K2_KL (3*T2_US)
#define K2_VH (4*T2_US)
#define K2_VL (5*T2_US)
#define K2_PH (6*T2_US)
#define K2_PL (7*T2_US)
#define K2_ATT_F 18432
#define K2_BIAS_F (K2_ATT_F + 3712)
#define K2_INTS_F (K2_BIAS_F + 338)
#define K2_SMEM_BYTES 90752

__global__ void __launch_bounds__(256, 2)
swin_attn_mma_kernel(const unsigned short* __restrict__ qhi,
                     const unsigned short* __restrict__ qlo,
                     const float* __restrict__ table,
                     unsigned short* __restrict__ ahi,
                     unsigned short* __restrict__ alo)
{
    extern __shared__ float sf[];
    unsigned short* su = (unsigned short*)sf;
    float* attnS = sf + K2_ATT_F;          // [64][58]
    float* biasP = sf + K2_BIAS_F;         // [2][169]
    int*   tokS  = (int*)(sf + K2_INTS_F);
    int*   regS  = tokS + 49;
    int*   rowS  = regS + 49;
    int*   colS  = rowS + 49;

    const int tid  = threadIdx.x;
    const int lane = tid & 31;
    const int wid  = tid >> 5;
    const int mt   = wid & 3;
    const int nh   = wid >> 2;
    const int w    = blockIdx.x;
    const int hp   = blockIdx.y;          // head pair 0..5
    const int b    = w >> 6;
    const int wi   = w & 63;
    const int wr   = wi >> 3;
    const int wc   = wi & 7;

    const uint32_t sb = smem_u32(su);
    const int lr = lane & 7, lq = lane >> 3;
    const uint32_t aoff =
        (uint32_t)((((lq & 1) * 8 + lr) * 72 + (lq >> 1) * 8) * 2);
    const uint32_t boff =
        (uint32_t)((((lq >> 1) * 8 + lr) * 72 + (lq & 1) * 8) * 2);

    {
        unsigned long long* z = (unsigned long long*)su;
        for (int i = tid; i < 8 * T2_US / 4; i += 256) z[i] = 0ull;
    }

    if (tid < 49) {
        int tr = tid / 7, tc = tid - tr * 7;
        rowS[tid] = tr; colS[tid] = tc;
        int gr = wr * 7 + tr, gc = wc * 7 + tc;
        int rh = (gr < 49) ? 0 : (gr < 53 ? 1 : 2);
        int rw = (gc < 49) ? 0 : (gc < 53 ? 1 : 2);
        regS[tid] = rh * 3 + rw;
        int sr = gr + 3; if (sr >= 56) sr -= 56;
        int sc = gc + 3; if (sc >= 56) sc -= 56;
        tokS[tid] = (b * 56 + sr) * 56 + sc;
    }
    for (int i = tid; i < 338; i += 256) {
        int hh = (i >= 169) ? 1 : 0;
        biasP[i] = table[(i - 169 * hh) * 12 + 2 * hp + hh];
    }
    __syncthreads();

    for (int i = tid; i < 2352; i += 256) {
        int t = i / 48;
        int r = i - t * 48;
        int s = r >> 4;
        int q = r & 15;
        int half = q >> 3;
        int c8 = q & 7;
        const unsigned short* src = (half ? qlo : qhi)
            + (size_t)tokS[t] * 1152 + s * 384 + hp * 64 + c8 * 8;
        uint32_t dst = sb + (uint32_t)(((s * 2 + half) * T2_US
                        + t * 72 + c8 * 8) * 2);
        CPA16(dst, src);
    }
    CPA_COMMIT();
    CPA_WAIT0();
    __syncthreads();

    for (int h = 0; h < 2; ++h) {
        // ================= QK^T ================
        {
            uint32_t qh[2][4], ql[2][4];
            #pragma unroll
            for (int ks = 0; ks < 2; ++ks) {
                uint32_t base = (uint32_t)((mt * 16) * 144
                                + (h * 32 + ks * 16) * 2);
                LDM4(qh[ks][0], qh[ks][1], qh[ks][2], qh[ks][3],
                     sb + K2_QH * 2 + base + aoff);
                LDM4(ql[ks][0], ql[ks][1], ql[ks][2], ql[ks][3],
                     sb + K2_QL * 2 + base + aoff);
            }
            float c[4][4];
            #pragma unroll
            for (int nt = 0; nt < 4; ++nt)
                #pragma unroll
                for (int i = 0; i < 4; ++i) c[nt][i] = 0.f;

            #pragma unroll
            for (int ks = 0; ks < 2; ++ks) {
                uint32_t kh[4][2], kl[4][2];
                #pragma unroll
                for (int lp = 0; lp < 2; ++lp) {
                    int ntp = nh * 2 + lp;
                    uint32_t base = (uint32_t)((ntp * 16) * 144
                                    + (h * 32 + ks * 16) * 2);
                    LDM4(kh[2*lp][0], kh[2*lp][1], kh[2*lp+1][0], kh[2*lp+1][1],
                         sb + K2_KH * 2 + base + boff);
                    LDM4(kl[2*lp][0], kl[2*lp][1], kl[2*lp+1][0], kl[2*lp+1][1],
                         sb + K2_KL * 2 + base + boff);
                }
                #pragma unroll
                for (int nt = 0; nt < 4; ++nt) {
                    MMA_BF16(c[nt], qh[ks], kh[nt]);
                    MMA_BF16(c[nt], qh[ks], kl[nt]);
                    MMA_BF16(c[nt], ql[ks], kh[nt]);
                }
            }
            #pragma unroll
            for (int nt = 0; nt < 4; ++nt) {
                int gnt = nh * 4 + nt;
                if (gnt == 7) continue;
                int row = mt * 16 + (lane >> 2);
                int col = gnt * 8 + (lane & 3) * 2;
                *(float2*)(attnS + row * 58 + col) =
                    make_float2(c[nt][0], c[nt][1]);
                *(float2*)(attnS + (row + 8) * 58 + col) =
                    make_float2(c[nt][2], c[nt][3]);
            }
        }
        __syncthreads();

        // ================= softmax -> P hi/lo ==============
        for (int row = wid; row < 49; row += 8) {
            const float* ap = attnS + row * 58;
            int ri = rowS[row], ci = colS[row], rg = regS[row];
            float v0, v1;
            {
                int j = lane;
                if (j < 49) {
                    int rel = (ri - rowS[j] + 6) * 13 + (ci - colS[j] + 6);
                    v0 = ap[j] + biasP[h * 169 + rel];
                    if (rg != regS[j]) v0 -= 100.0f;
                } else v0 = -3.0e38f;
            }
            {
                int j = 32 + lane;
                if (j < 49) {
                    int rel = (ri - rowS[j] + 6) * 13 + (ci - colS[j] + 6);
                    v1 = ap[j] + biasP[h * 169 + rel];
                    if (rg != regS[j]) v1 -= 100.0f;
                } else v1 = -3.0e38f;
            }
            float m = fmaxf(v0, v1);
            #pragma unroll
            for (int off = 16; off; off >>= 1)
                m = fmaxf(m, __shfl_xor_sync(0xffffffffu, m, off));
            float e0 = (lane < 49) ? __expf(v0 - m) : 0.f;
            float e1 = (32 + lane < 49) ? __expf(v1 - m) : 0.f;
            float s = e0 + e1;
            #pragma unroll
            for (int off = 16; off; off >>= 1)
                s += __shfl_xor_sync(0xffffffffu, s, off);
            float inv = 1.0f / s;
            unsigned short ph, pl;
            cvt_split(e0 * inv, ph, pl);
            su[K2_PH + row * 72 + lane] = ph;
            su[K2_PL + row * 72 + lane] = pl;
            if (32 + lane < 49) {
                cvt_split(e1 * inv, ph, pl);
                su[K2_PH + row * 72 + 32 + lane] = ph;
                su[K2_PL + row * 72 + 32 + lane] = pl;
            }
        }
        __syncthreads();

        // ================= out = P @ V ==============
        {
            float c2[2][4];
            #pragma unroll
            for (int dt = 0; dt < 2; ++dt)
                #pragma unroll
                for (int i = 0; i < 4; ++i) c2[dt][i] = 0.f;

            const uint32_t vlo =
                (uint32_t)((((lq & 1) * 8 + lr) * 144)
                           + ((h * 32 + nh * 16 + (lq >> 1) * 8) * 2));

            #pragma unroll
            for (int ks = 0; ks < 4; ++ks) {
                uint32_t aPh[4], aPl[4];
                uint32_t base = (uint32_t)((mt * 16) * 144 + ks * 32);
                LDM4(aPh[0], aPh[1], aPh[2], aPh[3],
                     sb + K2_PH * 2 + base + aoff);
                LDM4(aPl[0], aPl[1], aPl[2], aPl[3],
                     sb + K2_PL * 2 + base + aoff);

                uint32_t vh[2][2], vl[2][2];
                uint32_t vbase = (uint32_t)((16 * ks) * 144);
                LDM4T(vh[0][0], vh[0][1], vh[1][0], vh[1][1],
                      sb + K2_VH * 2 + vbase + vlo);
                LDM4T(vl[0][0], vl[0][1], vl[1][0], vl[1][1],
                      sb + K2_VL * 2 + vbase + vlo);

                #pragma unroll
                for (int dt = 0; dt < 2; ++dt) {
                    MMA_BF16(c2[dt], aPh, vh[dt]);
                    MMA_BF16(c2[dt], aPh, vl[dt]);
                    MMA_BF16(c2[dt], aPl, vh[dt]);
                }
            }
            #pragma unroll
            for (int dt = 0; dt < 2; ++dt) {
                int r0 = mt * 16 + (lane >> 2);
                int col = (2 * hp + h) * 32 + (nh * 2 + dt) * 8
                          + (lane & 3) * 2;
                if (r0 < 49) {
                    unsigned short hx, lx, hy, ly;
                    cvt_split(c2[dt][0], hx, lx);
                    cvt_split(c2[dt][1], hy, ly);
                    size_t o = (size_t)tokS[r0] * 384 + col;
                    *(ushort2*)(ahi + o) = make_ushort2(hx, hy);
                    *(ushort2*)(alo + o) = make_ushort2(lx, ly);
                }
                int r1 = r0 + 8;
                if (r1 < 49) {
                    unsigned short hx, lx, hy, ly;
                    cvt_split(c2[dt][2], hx, lx);
                    cvt_split(c2[dt][3], hy, ly);
                    size_t o = (size_t)tokS[r1] * 384 + col;
                    *(ushort2*)(ahi + o) = make_ushort2(hx, hy);
                    *(ushort2*)(alo + o) = make_ushort2(lx, ly);
                }
            }
        }
        if (h == 0) __syncthreads();
    }
}

// ============================================================================
extern "C" void kernel_launch(void* const* d_in, const int* in_sizes, int n_in,
                              void* d_out, int out_size)
{
    const float* x     = (const float*)d_in[0];
    const float* qkvw  = (const float*)d_in[1];
    const float* qkvb  = (const float*)d_in[2];
    const float* projw = (const float*)d_in[3];
    const float* projb = (const float*)d_in[4];
    const float* table = (const float*)d_in[5];
    float* out = (float*)d_out;

    unsigned short *qhi, *qlo, *xhi, *xlo, *ahi, *alo, *whi, *wlo, *phi, *plo;
    cudaGetSymbolAddress((void**)&qhi, g_qhi);
    cudaGetSymbolAddress((void**)&qlo, g_qlo);
    cudaGetSymbolAddress((void**)&xhi, g_xhi);
    cudaGetSymbolAddress((void**)&xlo, g_xlo);
    cudaGetSymbolAddress((void**)&ahi, g_ahi);
    cudaGetSymbolAddress((void**)&alo, g_alo);
    cudaGetSymbolAddress((void**)&whi, g_whi);
    cudaGetSymbolAddress((void**)&wlo, g_wlo);
    cudaGetSymbolAddress((void**)&phi, g_phi);
    cudaGetSymbolAddress((void**)&plo, g_plo);

    cudaFuncSetAttribute(gemm_bf16x3_kernel,
                         cudaFuncAttributeMaxDynamicSharedMemorySize, GSMEM_BYTES);
    cudaFuncSetAttribute(swin_attn_mma_kernel,
                         cudaFuncAttributeMaxDynamicSharedMemorySize, K2_SMEM_BYTES);

    split_bf16_kernel<<<18816, 256>>>((const float4*)x, (ushort4*)xhi,
                                      (ushort4*)xlo, 4816896);
    split_bf16_kernel<<<432, 256>>>((const float4*)qkvw, (ushort4*)whi,
                                    (ushort4*)wlo, 110592);
    split_bf16_kernel<<<144, 256>>>((const float4*)projw, (ushort4*)phi,
                                    (ushort4*)plo, 36864);

    gemm_bf16x3_kernel<<<dim3(392, 9), 256, GSMEM_BYTES>>>(
        xhi, xlo, whi, wlo, qkvb, nullptr, qhi, qlo, 1152, 1);
    swin_attn_mma_kernel<<<dim3(1024, 6), 256, K2_SMEM_BYTES>>>(
        qhi, qlo, table, ahi, alo);
    gemm_bf16x3_kernel<<<dim3(392, 3), 256, GSMEM_BYTES>>>(
        ahi, alo, phi, plo, projb, out, nullptr, nullptr, 384, 0);
}

// round 17
// speedup vs baseline: 1.5514x; 1.0072x over previous
#include <cuda_runtime.h>
#include <cuda_bf16.h>
#include <cstdint>

// ============================================================================
// Shifted-window attention pipeline:
//   K0: split X / qkvw / projw into bf16 (hi, lo) pairs        (elementwise)
//   K1: qkv(hi,lo) = X @ qkvw^T + qkvb   (bf16 3-term MMA, 128x128 tile,
//        K-chunk 32, 2-stage cp.async(.cg), single-barrier pipeline)
//   K2: per-(window, head-pair) attention, staging overlapped with preamble
//   K3: out = attno @ projw^T + projb    (same GEMM, fp32 out)
// ============================================================================

#define KDIM 384
#define NTOKENS 50176   // 16*56*56 = 392*128

static __device__ unsigned short g_qhi[(size_t)NTOKENS * 1152];
static __device__ unsigned short g_qlo[(size_t)NTOKENS * 1152];
static __device__ unsigned short g_xhi[(size_t)NTOKENS * 384];
static __device__ unsigned short g_xlo[(size_t)NTOKENS * 384];
static __device__ unsigned short g_ahi[(size_t)NTOKENS * 384];
static __device__ unsigned short g_alo[(size_t)NTOKENS * 384];
static __device__ unsigned short g_whi[1152 * 384];
static __device__ unsigned short g_wlo[1152 * 384];
static __device__ unsigned short g_phi[384 * 384];
static __device__ unsigned short g_plo[384 * 384];

__device__ __forceinline__ uint32_t smem_u32(const void* p) {
    uint32_t a;
    asm("{ .reg .u64 t; cvta.to.shared.u64 t, %1; cvt.u32.u64 %0, t; }"
        : "=r"(a) : "l"(p));
    return a;
}
#define LDM4(r0, r1, r2, r3, addr)                                           \
    asm volatile("ldmatrix.sync.aligned.m8n8.x4.shared.b16 {%0,%1,%2,%3}, [%4];" \
                 : "=r"(r0), "=r"(r1), "=r"(r2), "=r"(r3) : "r"(addr))
#define LDM4T(r0, r1, r2, r3, addr)                                          \
    asm volatile("ldmatrix.sync.aligned.m8n8.x4.trans.shared.b16 {%0,%1,%2,%3}, [%4];" \
                 : "=r"(r0), "=r"(r1), "=r"(r2), "=r"(r3) : "r"(addr))
#define MMA_BF16(c, a, b)                                                    \
    asm volatile("mma.sync.aligned.m16n8k16.row.col.f32.bf16.bf16.f32 "      \
                 "{%0,%1,%2,%3}, {%4,%5,%6,%7}, {%8,%9}, {%0,%1,%2,%3};"     \
                 : "+f"((c)[0]), "+f"((c)[1]), "+f"((c)[2]), "+f"((c)[3])    \
                 : "r"((a)[0]), "r"((a)[1]), "r"((a)[2]), "r"((a)[3]),       \
                   "r"((b)[0]), "r"((b)[1]))
#define CPA16(dst, src)                                                      \
    asm volatile("cp.async.cg.shared.global [%0], [%1], 16;" :: "r"(dst), "l"(src))
#define CPA_COMMIT() asm volatile("cp.async.commit_group;")
#define CPA_WAIT0()  asm volatile("cp.async.wait_group 0;")

__device__ __forceinline__ void cvt_split(float x, unsigned short& h,
                                          unsigned short& l) {
    __nv_bfloat16 bh = __float2bfloat16_rn(x);
    h = __bfloat16_as_ushort(bh);
    l = __bfloat16_as_ushort(__float2bfloat16_rn(x - __bfloat162float(bh)));
}

// ============================================================================
// K0: fp32 -> bf16 hi/lo split
// ============================================================================
__global__ void __launch_bounds__(256)
split_bf16_kernel(const float4* __restrict__ in, ushort4* __restrict__ hi,
                  ushort4* __restrict__ lo, int n4)
{
    int i = blockIdx.x * 256 + threadIdx.x;
    if (i >= n4) return;
    float4 v = in[i];
    ushort4 h, l;
    cvt_split(v.x, h.x, l.x);
    cvt_split(v.y, h.y, l.y);
    cvt_split(v.z, h.z, l.z);
    cvt_split(v.w, h.w, l.w);
    hi[i] = h;
    lo[i] = l;
}

// ============================================================================
// K1/K3 GEMM (R15-proven: single-barrier 2-stage pipeline, 2 CTAs/SM)
// ============================================================================
#define GSTR 40
#define TILE_US (128 * GSTR)            // 5120
#define STAGE_US (4 * TILE_US)          // 20480
#define GSMEM_BYTES (2 * STAGE_US * 2)  // 81920

__global__ void __launch_bounds__(256, 2)
gemm_bf16x3_kernel(const unsigned short* __restrict__ Ahi_g,
                   const unsigned short* __restrict__ Alo_g,
                   const unsigned short* __restrict__ Bhi_g,
                   const unsigned short* __restrict__ Blo_g,
                   const float* __restrict__ bias, float* __restrict__ C,
                   unsigned short* __restrict__ Chi,
                   unsigned short* __restrict__ Clo,
                   int ncols, int qflag)
{
    extern __shared__ __align__(16) unsigned short gsm[];

    const int tid  = threadIdx.x;
    const int lane = tid & 31;
    const int wid  = tid >> 5;
    const int wm   = wid & 3;
    const int wn   = wid >> 2;
    const int mbase = blockIdx.x * 128;
    const int nbase = blockIdx.y * 128;
    const uint32_t sbase = smem_u32(gsm);

    const int lr = lane & 7, lq = lane >> 3;
    const uint32_t aoff =
        (uint32_t)((((lq & 1) * 8 + lr) * GSTR + (lq >> 1) * 8) * 2);
    const uint32_t boff =
        (uint32_t)((((lq >> 1) * 8 + lr) * GSTR + (lq & 1) * 8) * 2);

    float c[2][8][4];
    #pragma unroll
    for (int mt = 0; mt < 2; ++mt)
        #pragma unroll
        for (int nt = 0; nt < 8; ++nt)
            #pragma unroll
            for (int i = 0; i < 4; ++i) c[mt][nt][i] = 0.f;

    auto prefetch = [&](int sbuf, int kc) {
        const uint32_t st = sbase + (uint32_t)sbuf * (STAGE_US * 2);
        #pragma unroll
        for (int j = 0; j < 8; ++j) {
            int cch = tid + 256 * j;
            int tile = cch >> 9;
            int rc = cch & 511;
            int row = rc >> 2, c8 = rc & 3;
            uint32_t doff = (uint32_t)(tile * (TILE_US * 2) + row * 80 + c8 * 16);
            const unsigned short* srcb;
            size_t idx;
            if (tile < 2) {
                srcb = (tile & 1) ? Alo_g : Ahi_g;
                idx = (size_t)(mbase + row) * KDIM + kc * 32 + c8 * 8;
            } else {
                srcb = (tile & 1) ? Blo_g : Bhi_g;
                idx = (size_t)(nbase + row) * KDIM + kc * 32 + c8 * 8;
            }
            CPA16(st + doff, srcb + idx);
        }
        CPA_COMMIT();
    };

    prefetch(0, 0);

    for (int kc = 0; kc < 12; ++kc) {
        CPA_WAIT0();
        __syncthreads();
        if (kc + 1 < 12) prefetch((kc + 1) & 1, kc + 1);

        const uint32_t st = sbase + (uint32_t)(kc & 1) * (STAGE_US * 2);
        const uint32_t sAhi = st;
        const uint32_t sAlo = st + TILE_US * 2;
        const uint32_t sBhi = st + 2 * TILE_US * 2;
        const uint32_t sBlo = st + 3 * TILE_US * 2;

        #pragma unroll
        for (int ks = 0; ks < 2; ++ks) {
            const uint32_t kb = (uint32_t)(ks * 32);
            uint32_t ah[2][4], al[2][4];
            #pragma unroll
            for (int mt = 0; mt < 2; ++mt) {
                uint32_t base = (uint32_t)((wm * 32 + mt * 16) * (GSTR * 2)) + kb;
                LDM4(ah[mt][0], ah[mt][1], ah[mt][2], ah[mt][3], sAhi + base + aoff);
                LDM4(al[mt][0], al[mt][1], al[mt][2], al[mt][3], sAlo + base + aoff);
            }
            #pragma unroll
            for (int ntp = 0; ntp < 4; ++ntp) {
                uint32_t bh[2][2], bl[2][2];
                uint32_t base = (uint32_t)((wn * 64 + ntp * 16) * (GSTR * 2)) + kb;
                LDM4(bh[0][0], bh[0][1], bh[1][0], bh[1][1], sBhi + base + boff);
                LDM4(bl[0][0], bl[0][1], bl[1][0], bl[1][1], sBlo + base + boff);
                #pragma unroll
                for (int mt = 0; mt < 2; ++mt)
                    #pragma unroll
                    for (int j = 0; j < 2; ++j) {
                        MMA_BF16(c[mt][ntp * 2 + j], ah[mt], bh[j]);
                        MMA_BF16(c[mt][ntp * 2 + j], ah[mt], bl[j]);
                        MMA_BF16(c[mt][ntp * 2 + j], al[mt], bh[j]);
                    }
            }
        }
    }

    const float qscale = 0.17677669529663687f;
    #pragma unroll
    for (int mt = 0; mt < 2; ++mt) {
        #pragma unroll
        for (int nt = 0; nt < 8; ++nt) {
            int row0 = mbase + wm * 32 + mt * 16 + (lane >> 2);
            int col  = nbase + wn * 64 + nt * 8 + (lane & 3) * 2;
            float sc = (qflag && col < 384) ? qscale : 1.0f;
            float b0 = __ldg(bias + col), b1 = __ldg(bias + col + 1);
            float v00 = (c[mt][nt][0] + b0) * sc;
            float v01 = (c[mt][nt][1] + b1) * sc;
            float v10 = (c[mt][nt][2] + b0) * sc;
            float v11 = (c[mt][nt][3] + b1) * sc;
            if (Chi != nullptr) {
                unsigned short h0, l0, h1, l1;
                cvt_split(v00, h0, l0); cvt_split(v01, h1, l1);
                *(ushort2*)(Chi + (size_t)row0 * ncols + col) = make_ushort2(h0, h1);
                *(ushort2*)(Clo + (size_t)row0 * ncols + col) = make_ushort2(l0, l1);
                cvt_split(v10, h0, l0); cvt_split(v11, h1, l1);
                *(ushort2*)(Chi + (size_t)(row0 + 8) * ncols + col) = make_ushort2(h0, h1);
                *(ushort2*)(Clo + (size_t)(row0 + 8) * ncols + col) = make_ushort2(l0, l1);
            } else {
                *(float2*)(C + (size_t)row0 * ncols + col) = make_float2(v00, v01);
                *(float2*)(C + (size_t)(row0 + 8) * ncols + col) = make_float2(v10, v11);
            }
        }
    }
}

// ============================================================================
// K2: attention, one CTA per (window, head-pair). grid (1024, 6).
// Staging cp.async issued FIRST (inline token math); pad-only zeroing and
// table setup overlap the load latency; single wait+sync.
// ============================================================================
#define T2_US 4608            // 64*72
#define K2_QH 0
#define K2_QL (1*T2_US)
#define K2_KH (2*T2_US)
#define K2_KL (3*T2_US)
#define K2_VH (4*T2_US)
#define K2_VL (5*T2_US)
#define K2_PH (6*T2_US)
#define K2_PL (7*T2_US)
#define K2_ATT_F 18432
#define K2_BIAS_F (K2_ATT_F + 3712)
#define K2_INTS_F (K2_BIAS_F + 338)
#define K2_SMEM_BYTES 90752

__global__ void __launch_bounds__(256, 2)
swin_attn_mma_kernel(const unsigned short* __restrict__ qhi,
                     const unsigned short* __restrict__ qlo,
                     const float* __restrict__ table,
                     unsigned short* __restrict__ ahi,
                     unsigned short* __restrict__ alo)
{
    extern __shared__ float sf[];
    unsigned short* su = (unsigned short*)sf;
    float* attnS = sf + K2_ATT_F;          // [64][58]
    float* biasP = sf + K2_BIAS_F;         // [2][169]
    int*   tokS  = (int*)(sf + K2_INTS_F);
    int*   regS  = tokS + 49;
    int*   rowS  = regS + 49;
    int*   colS  = rowS + 49;

    const int tid  = threadIdx.x;
    const int lane = tid & 31;
    const int wid  = tid >> 5;
    const int mt   = wid & 3;
    const int nh   = wid >> 2;
    const int w    = blockIdx.x;
    const int hp   = blockIdx.y;          // head pair 0..5
    const int b    = w >> 6;
    const int wi   = w & 63;
    const int wr   = wi >> 3;
    const int wc   = wi & 7;

    const uint32_t sb = smem_u32(su);
    const int lr = lane & 7, lq = lane >> 3;
    const uint32_t aoff =
        (uint32_t)((((lq & 1) * 8 + lr) * 72 + (lq >> 1) * 8) * 2);
    const uint32_t boff =
        (uint32_t)((((lq >> 1) * 8 + lr) * 72 + (lq & 1) * 8) * 2);

    // ---- 1) issue staging cp.asyncs immediately (inline token index) ----
    for (int i = tid; i < 2352; i += 256) {
        int t = i / 48;
        int r = i - t * 48;
        int s = r >> 4;
        int q = r & 15;
        int half = q >> 3;
        int c8 = q & 7;
        int tr = t / 7, tc = t - tr * 7;
        int sr = wr * 7 + tr + 3; if (sr >= 56) sr -= 56;
        int sc = wc * 7 + tc + 3; if (sc >= 56) sc -= 56;
        int tok = (b * 56 + sr) * 56 + sc;
        const unsigned short* src = (half ? qlo : qhi)
            + (size_t)tok * 1152 + s * 384 + hp * 64 + c8 * 8;
        uint32_t dst = sb + (uint32_t)(((s * 2 + half) * T2_US
                        + t * 72 + c8 * 8) * 2);
        CPA16(dst, src);
    }
    CPA_COMMIT();

    // ---- 2) pad-only zeroing (never touches cp.async destinations) ----
    {
        unsigned long long* z = (unsigned long long*)su;
        // rows 49-63, full stride, all 8 tiles: 270 ull per tile
        for (int i = tid; i < 2160; i += 256) {
            int tile = i / 270;
            int o = i - tile * 270;
            z[tile * 1152 + 882 + o] = 0ull;   // 3528 shorts / 4 = 882
        }
        // rows 0-48, cols 64-71, all 8 tiles: 2 ull per row
        for (int i = tid; i < 784; i += 256) {
            int tile = i / 98;
            int rem = i - tile * 98;
            int row = rem >> 1, p = rem & 1;
            z[tile * 1152 + row * 18 + 16 + p] = 0ull;
        }
        // P tiles (6,7): rows 0-48, cols 48-63 (softmax rewrites col 48)
        for (int i = tid; i < 392; i += 256) {
            int tt = i / 196;
            int rem = i - tt * 196;
            int row = rem >> 2, p = rem & 3;
            z[(6 + tt) * 1152 + row * 18 + 12 + p] = 0ull;
        }
    }

    // ---- 3) token tables + bias (overlaps load latency) ----
    if (tid < 49) {
        int tr = tid / 7, tc = tid - tr * 7;
        rowS[tid] = tr; colS[tid] = tc;
        int gr = wr * 7 + tr, gc = wc * 7 + tc;
        int rh = (gr < 49) ? 0 : (gr < 53 ? 1 : 2);
        int rw = (gc < 49) ? 0 : (gc < 53 ? 1 : 2);
        regS[tid] = rh * 3 + rw;
        int sr = gr + 3; if (sr >= 56) sr -= 56;
        int sc = gc + 3; if (sc >= 56) sc -= 56;
        tokS[tid] = (b * 56 + sr) * 56 + sc;
    }
    for (int i = tid; i < 338; i += 256) {
        int hh = (i >= 169) ? 1 : 0;
        biasP[i] = table[(i - 169 * hh) * 12 + 2 * hp + hh];
    }

    CPA_WAIT0();
    __syncthreads();

    for (int h = 0; h < 2; ++h) {
        // ================= QK^T ================
        {
            uint32_t qh[2][4], ql[2][4];
            #pragma unroll
            for (int ks = 0; ks < 2; ++ks) {
                uint32_t base = (uint32_t)((mt * 16) * 144
                                + (h * 32 + ks * 16) * 2);
                LDM4(qh[ks][0], qh[ks][1], qh[ks][2], qh[ks][3],
                     sb + K2_QH * 2 + base + aoff);
                LDM4(ql[ks][0], ql[ks][1], ql[ks][2], ql[ks][3],
                     sb + K2_QL * 2 + base + aoff);
            }
            float c[4][4];
            #pragma unroll
            for (int nt = 0; nt < 4; ++nt)
                #pragma unroll
                for (int i = 0; i < 4; ++i) c[nt][i] = 0.f;

            #pragma unroll
            for (int ks = 0; ks < 2; ++ks) {
                uint32_t kh[4][2], kl[4][2];
                #pragma unroll
                for (int lp = 0; lp < 2; ++lp) {
                    int ntp = nh * 2 + lp;
                    uint32_t base = (uint32_t)((ntp * 16) * 144
                                    + (h * 32 + ks * 16) * 2);
                    LDM4(kh[2*lp][0], kh[2*lp][1], kh[2*lp+1][0], kh[2*lp+1][1],
                         sb + K2_KH * 2 + base + boff);
                    LDM4(kl[2*lp][0], kl[2*lp][1], kl[2*lp+1][0], kl[2*lp+1][1],
                         sb + K2_KL * 2 + base + boff);
                }
                #pragma unroll
                for (int nt = 0; nt < 4; ++nt) {
                    MMA_BF16(c[nt], qh[ks], kh[nt]);
                    MMA_BF16(c[nt], qh[ks], kl[nt]);
                    MMA_BF16(c[nt], ql[ks], kh[nt]);
                }
            }
            #pragma unroll
            for (int nt = 0; nt < 4; ++nt) {
                int gnt = nh * 4 + nt;
                if (gnt == 7) continue;
                int row = mt * 16 + (lane >> 2);
                int col = gnt * 8 + (lane & 3) * 2;
                *(float2*)(attnS + row * 58 + col) =
                    make_float2(c[nt][0], c[nt][1]);
                *(float2*)(attnS + (row + 8) * 58 + col) =
                    make_float2(c[nt][2], c[nt][3]);
            }
        }
        __syncthreads();

        // ================= softmax -> P hi/lo ==============
        for (int row = wid; row < 49; row += 8) {
            const float* ap = attnS + row * 58;
            int ri = rowS[row], ci = colS[row], rg = regS[row];
            float v0, v1;
            {
                int j = lane;
                if (j < 49) {
                    int rel = (ri - rowS[j] + 6) * 13 + (ci - colS[j] + 6);
                    v0 = ap[j] + biasP[h * 169 + rel];
                    if (rg != regS[j]) v0 -= 100.0f;
                } else v0 = -3.0e38f;
            }
            {
                int j = 32 + lane;
                if (j < 49) {
                    int rel = (ri - rowS[j] + 6) * 13 + (ci - colS[j] + 6);
                    v1 = ap[j] + biasP[h * 169 + rel];
                    if (rg != regS[j]) v1 -= 100.0f;
                } else v1 = -3.0e38f;
            }
            float m = fmaxf(v0, v1);
            #pragma unroll
            for (int off = 16; off; off >>= 1)
                m = fmaxf(m, __shfl_xor_sync(0xffffffffu, m, off));
            float e0 = (lane < 49) ? __expf(v0 - m) : 0.f;
            float e1 = (32 + lane < 49) ? __expf(v1 - m) : 0.f;
            float s = e0 + e1;
            #pragma unroll
            for (int off = 16; off; off >>= 1)
                s += __shfl_xor_sync(0xffffffffu, s, off);
            float inv = 1.0f / s;
            unsigned short ph, pl;
            cvt_split(e0 * inv, ph, pl);
            su[K2_PH + row * 72 + lane] = ph;
            su[K2_PL + row * 72 + lane] = pl;
            if (32 + lane < 49) {
                cvt_split(e1 * inv, ph, pl);
                su[K2_PH + row * 72 + 32 + lane] = ph;
                su[K2_PL + row * 72 + 32 + lane] = pl;
            }
        }
        __syncthreads();

        // ================= out = P @ V ==============
        {
            float c2[2][4];
            #pragma unroll
            for (int dt = 0; dt < 2; ++dt)
                #pragma unroll
                for (int i = 0; i < 4; ++i) c2[dt][i] = 0.f;

            const uint32_t vlo =
                (uint32_t)((((lq & 1) * 8 + lr) * 144)
                           + ((h * 32 + nh * 16 + (lq >> 1) * 8) * 2));

            #pragma unroll
            for (int ks = 0; ks < 4; ++ks) {
                uint32_t aPh[4], aPl[4];
                uint32_t base = (uint32_t)((mt * 16) * 144 + ks * 32);
                LDM4(aPh[0], aPh[1], aPh[2], aPh[3],
                     sb + K2_PH * 2 + base + aoff);
                LDM4(aPl[0], aPl[1], aPl[2], aPl[3],
                     sb + K2_PL * 2 + base + aoff);

                uint32_t vh[2][2], vl[2][2];
                uint32_t vbase = (uint32_t)((16 * ks) * 144);
                LDM4T(vh[0][0], vh[0][1], vh[1][0], vh[1][1],
                      sb + K2_VH * 2 + vbase + vlo);
                LDM4T(vl[0][0], vl[0][1], vl[1][0], vl[1][1],
                      sb + K2_VL * 2 + vbase + vlo);

                #pragma unroll
                for (int dt = 0; dt < 2; ++dt) {
                    MMA_BF16(c2[dt], aPh, vh[dt]);
                    MMA_BF16(c2[dt], aPh, vl[dt]);
                    MMA_BF16(c2[dt], aPl, vh[dt]);
                }
            }
            #pragma unroll
            for (int dt = 0; dt < 2; ++dt) {
                int r0 = mt * 16 + (lane >> 2);
                int col = (2 * hp + h) * 32 + (nh * 2 + dt) * 8
                          + (lane & 3) * 2;
                if (r0 < 49) {
                    unsigned short hx, lx, hy, ly;
                    cvt_split(c2[dt][0], hx, lx);
                    cvt_split(c2[dt][1], hy, ly);
                    size_t o = (size_t)tokS[r0] * 384 + col;
                    *(ushort2*)(ahi + o) = make_ushort2(hx, hy);
                    *(ushort2*)(alo + o) = make_ushort2(lx, ly);
                }
                int r1 = r0 + 8;
                if (r1 < 49) {
                    unsigned short hx, lx, hy, ly;
                    cvt_split(c2[dt][2], hx, lx);
                    cvt_split(c2[dt][3], hy, ly);
                    size_t o = (size_t)tokS[r1] * 384 + col;
                    *(ushort2*)(ahi + o) = make_ushort2(hx, hy);
                    *(ushort2*)(alo + o) = make_ushort2(lx, ly);
                }
            }
        }
        if (h == 0) __syncthreads();
    }
}

// ============================================================================
extern "C" void kernel_launch(void* const* d_in, const int* in_sizes, int n_in,
                              void* d_out, int out_size)
{
    const float* x     = (const float*)d_in[0];
    const float* qkvw  = (const float*)d_in[1];
    const float* qkvb  = (const float*)d_in[2];
    const float* projw = (const float*)d_in[3];
    const float* projb = (const float*)d_in[4];
    const float* table = (const float*)d_in[5];
    float* out = (float*)d_out;

    unsigned short *qhi, *qlo, *xhi, *xlo, *ahi, *alo, *whi, *wlo, *phi, *plo;
    cudaGetSymbolAddress((void**)&qhi, g_qhi);
    cudaGetSymbolAddress((void**)&qlo, g_qlo);
    cudaGetSymbolAddress((void**)&xhi, g_xhi);
    cudaGetSymbolAddress((void**)&xlo, g_xlo);
    cudaGetSymbolAddress((void**)&ahi, g_ahi);
    cudaGetSymbolAddress((void**)&alo, g_alo);
    cudaGetSymbolAddress((void**)&whi, g_whi);
    cudaGetSymbolAddress((void**)&wlo, g_wlo);
    cudaGetSymbolAddress((void**)&phi, g_phi);
    cudaGetSymbolAddress((void**)&plo, g_plo);

    cudaFuncSetAttribute(gemm_bf16x3_kernel,
                         cudaFuncAttributeMaxDynamicSharedMemorySize, GSMEM_BYTES);
    cudaFuncSetAttribute(swin_attn_mma_kernel,
                         cudaFuncAttributeMaxDynamicSharedMemorySize, K2_SMEM_BYTES);

    split_bf16_kernel<<<18816, 256>>>((const float4*)x, (ushort4*)xhi,
                                      (ushort4*)xlo, 4816896);
    split_bf16_kernel<<<432, 256>>>((const float4*)qkvw, (ushort4*)whi,
                                    (ushort4*)wlo, 110592);
    split_bf16_kernel<<<144, 256>>>((const float4*)projw, (ushort4*)phi,
                                    (ushort4*)plo, 36864);

    gemm_bf16x3_kernel<<<dim3(392, 9), 256, GSMEM_BYTES>>>(
        xhi, xlo, whi, wlo, qkvb, nullptr, qhi, qlo, 1152, 1);
    swin_attn_mma_kernel<<<dim3(1024, 6), 256, K2_SMEM_BYTES>>>(
        qhi, qlo, table, ahi, alo);
    gemm_bf16x3_kernel<<<dim3(392, 3), 256, GSMEM_BYTES>>>(
        ahi, alo, phi, plo, projb, out, nullptr, nullptr, 384, 0);
}